// round 16
// baseline (speedup 1.0000x reference)
#include <cuda_runtime.h>
#include <cuda_fp16.h>
#include <math.h>
#include <stdint.h>

#define NTOK 4096
#define DMODEL 1024
#define D3 3072
#define NHEAD 16
#define HDIM 64
#define SEQ 1024
#define NB 4
#define NTILES 8
#define DFF 4096

// ---------------- scratch (device globals) -------------------------------------
__device__ __half g_qkv[NTOK * D3];
__device__ float g_xres[NTOK * DMODEL];
__device__ float g_n2[NTOK * DMODEL];
__device__ __half g_n1[NTOK * DMODEL];
__device__ __half g_attn[NTOK * DMODEL];
__device__ __half g_n2x[NTOK * DMODEL];
__device__ __half g_h[(size_t)NTOK * DFF];
__device__ __half g_qkvw[D3 * DMODEL];
__device__ __half g_outw[DMODEL * DMODEL];
__device__ __half g_upw[(size_t)NTILES * DMODEL * DFF];
__device__ __half g_dnw[(size_t)NTILES * DFF * DMODEL];
__device__ int g_tile_id[NTOK];
__device__ int g_perm[NTOK];
__device__ int g_cnt[NTILES];
__device__ int g_off[NTILES];
__device__ int g_fill[NTILES];

// ---------------- helpers -------------------------------------------------------
__device__ __forceinline__ uint32_t sptr(const void* p) {
    return (uint32_t)__cvta_generic_to_shared(p);
}
__device__ __forceinline__ uint32_t pack_h2(__half a, __half b) {
    return (uint32_t)__half_as_ushort(a) | ((uint32_t)__half_as_ushort(b) << 16);
}
__device__ __forceinline__ void conv4_h(float4 v, __half* d) {
    *(uint32_t*)(d)     = pack_h2(__float2half_rn(v.x), __float2half_rn(v.y));
    *(uint32_t*)(d + 2) = pack_h2(__float2half_rn(v.z), __float2half_rn(v.w));
}
__device__ __forceinline__ void ldsm4(uint32_t* r, uint32_t a) {
    asm volatile("ldmatrix.sync.aligned.m8n8.x4.shared.b16 {%0,%1,%2,%3}, [%4];"
                 : "=r"(r[0]), "=r"(r[1]), "=r"(r[2]), "=r"(r[3]) : "r"(a));
}
__device__ __forceinline__ void ldsm4t(uint32_t* r, uint32_t a) {
    asm volatile("ldmatrix.sync.aligned.m8n8.x4.trans.shared.b16 {%0,%1,%2,%3}, [%4];"
                 : "=r"(r[0]), "=r"(r[1]), "=r"(r[2]), "=r"(r[3]) : "r"(a));
}
__device__ __forceinline__ void mma16816(float* c, const uint32_t* a, const uint32_t* b) {
    asm volatile(
        "mma.sync.aligned.m16n8k16.row.col.f32.f16.f16.f32 "
        "{%0,%1,%2,%3}, {%4,%5,%6,%7}, {%8,%9}, {%0,%1,%2,%3};"
        : "+f"(c[0]), "+f"(c[1]), "+f"(c[2]), "+f"(c[3])
        : "r"(a[0]), "r"(a[1]), "r"(a[2]), "r"(a[3]), "r"(b[0]), "r"(b[1]));
}
__device__ __forceinline__ void cpa16(uint32_t s, const void* g) {
    asm volatile("cp.async.cg.shared.global [%0], [%1], 16;" :: "r"(s), "l"(g));
}
#define CP_COMMIT() asm volatile("cp.async.commit_group;" ::: "memory")
#define CP_WAIT2() asm volatile("cp.async.wait_group 2;" ::: "memory")
#define CP_WAIT0() asm volatile("cp.async.wait_group 0;" ::: "memory")

// ---------------- weight convert (8 floats / thread, 512-thr blocks) ---------------
__global__ void wconv(const float* __restrict__ src, __half* __restrict__ d) {
    size_t i = (size_t)blockIdx.x * 512 + threadIdx.x;
    float4 v0 = *(const float4*)(src + i * 8);
    float4 v1 = *(const float4*)(src + i * 8 + 4);
    conv4_h(v0, d + i * 8);
    conv4_h(v1, d + i * 8 + 4);
}

// ---------------- GEMM core: one 64-K chunk, warp tile 64x32 (M-tile 256) ---------
// A K-major stride 72 halves, 256 rows. B: BT=false K-major stride 72 (128 rows);
// BT=true MN-major stride 136 (64 k-rows x 128 n).
template <bool BT>
__device__ __forceinline__ void mma_compute(const __half* As, const __half* Bs,
                                            float (*acc)[4][4], int lane, int wm, int wn) {
#pragma unroll
    for (int s = 0; s < 4; s++) {
        const int ks = s * 16;
        uint32_t af[4][4], bf[4][2];
#pragma unroll
        for (int mi = 0; mi < 4; mi++) {
            int row = wm * 64 + mi * 16 + (lane & 15);
            int col = ks + ((lane >> 4) & 1) * 8;
            ldsm4(af[mi], sptr(As + row * 72 + col));
        }
#pragma unroll
        for (int p = 0; p < 2; p++) {
            uint32_t r[4];
            if (!BT) {
                int n = wn * 32 + p * 16 + ((lane >> 4) & 1) * 8 + (lane & 7);
                int col = ks + ((lane >> 3) & 1) * 8;
                ldsm4(r, sptr(Bs + n * 72 + col));
            } else {
                int k = ks + ((lane >> 3) & 1) * 8 + (lane & 7);
                int n = wn * 32 + p * 16 + ((lane >> 4) & 1) * 8;
                ldsm4t(r, sptr(Bs + k * 136 + n));
            }
            bf[2 * p][0] = r[0]; bf[2 * p][1] = r[1];
            bf[2 * p + 1][0] = r[2]; bf[2 * p + 1][1] = r[3];
        }
#pragma unroll
        for (int mi = 0; mi < 4; mi++)
#pragma unroll
            for (int ni = 0; ni < 4; ni++)
                mma16816(acc[mi][ni], af[mi], bf[ni]);
    }
}

// ---------------- GEMM: 512 thr, 256x128 tile, 64-K chunks, 4-stage ----------------
// MODE 0: +bias -> fp16 O          MODE 1: +bias +resid -> fp32 C
// MODE 2: gather A via perm, +bias, relu -> fp16 O (compact), BT
// MODE 3: A compact, +bias +resid, scatter -> fp32 C, BT
#define BOFFH 18432                 // halves offset of B in stage (A = 256*72)
#define STG_NT_H 27648              // halves per stage: A 18432 + B 128*72=9216
#define STG_T_H 27136               // halves per stage: A 18432 + B 64*136=8704

template <int MODE, bool BT>
__global__ __launch_bounds__(512, 1) void gemm_cp(
    const __half* __restrict__ Ah, const __half* __restrict__ W,
    const float* __restrict__ bias, const float* __restrict__ resid,
    float* __restrict__ C, __half* __restrict__ O, int N, int K) {
    constexpr int STGH = BT ? STG_T_H : STG_NT_H;
    extern __shared__ __half dsm[];
    const int tid = threadIdx.x, lane = tid & 31, w = tid >> 5;
    const int wm = w & 3, wn = w >> 2;
    const int bn = blockIdx.x * 128, bm = blockIdx.y * 256;
    int cnt = 0, off = 0;
    if (MODE >= 2) {
        const int t = blockIdx.z;
        cnt = g_cnt[t];
        if (bm >= cnt) return;
        off = g_off[t];
        W += (size_t)t * N * K;
        bias += (size_t)t * N;
    }
    const uint32_t sb = sptr(dsm);
    // A fill: row ar = tid>>1 (0..255); 4 x 16B at half-offset (tid&1)*32
    const int ar = tid >> 1, acb = (tid & 1) * 32;
    const uint32_t adst = (uint32_t)(ar * 144 + acb * 2);
    size_t abase;
    if (MODE <= 1) {
        abase = (size_t)(bm + ar) * K;
    } else if (MODE == 2) {
        int t0 = (bm + ar < cnt) ? g_perm[off + bm + ar] : 0;
        abase = (size_t)t0 * K;
    } else {
        int rc = (bm + ar < cnt) ? bm + ar : 0;
        abase = (size_t)(off + rc) * K;
    }
    // B fill
    size_t bbase = 0;
    uint32_t bdst = 0;
    int bcb = 0, bkr = 0, bnc = 0;
    if (!BT) {
        int br = tid >> 2;            // 0..127
        bcb = (tid & 3) * 16;         // halves: 2 x 16B
        bbase = (size_t)(bn + br) * K;
        bdst = (uint32_t)(BOFFH * 2 + br * 144 + bcb * 2);
    } else {
        bkr = tid >> 3;               // 0..63 (k row)
        bnc = (tid & 7) * 16;         // halves along n: 2 x 16B
        bdst = (uint32_t)(BOFFH * 2 + bkr * 272 + bnc * 2);
    }
    const int NC = K >> 6;
    auto fill = [&](int s, int c) {
        const int k0 = c * 64;
        const uint32_t st = sb + s * (STGH * 2);
#pragma unroll
        for (int i = 0; i < 4; i++)
            cpa16(st + adst + i * 16, Ah + abase + k0 + acb + i * 8);
        if (!BT) {
#pragma unroll
            for (int i = 0; i < 2; i++)
                cpa16(st + bdst + i * 16, W + bbase + k0 + bcb + i * 8);
        } else {
#pragma unroll
            for (int i = 0; i < 2; i++)
                cpa16(st + bdst + i * 16, W + (size_t)(k0 + bkr) * N + bn + bnc + i * 8);
        }
        CP_COMMIT();
    };
    fill(0, 0);
    if (NC > 1) fill(1, 1);
    if (NC > 2) fill(2, 2);
    float acc[4][4][4] = {};
    for (int c = 0; c < NC; c++) {
        if (c + 3 < NC) CP_WAIT2(); else CP_WAIT0();
        __syncthreads();  // data visible; all warps past chunk c-1's reads
        if (c + 3 < NC) fill((c + 3) & 3, c + 3);  // targets stage (c-1)&3: safe
        const __half* b0 = dsm + (c & 3) * STGH;
        mma_compute<BT>(b0, b0 + BOFFH, acc, lane, wm, wn);
    }
    // ---- epilogue
#pragma unroll
    for (int mi = 0; mi < 4; mi++) {
        int r0 = bm + wm * 64 + mi * 16 + (lane >> 2);
#pragma unroll
        for (int ni = 0; ni < 4; ni++) {
            int cn = bn + wn * 32 + ni * 8 + (lane & 3) * 2;
            float2 bs = *(const float2*)(bias + cn);
            if (MODE == 0) {
                *(uint32_t*)(O + (size_t)r0 * N + cn) =
                    pack_h2(__float2half_rn(acc[mi][ni][0] + bs.x),
                            __float2half_rn(acc[mi][ni][1] + bs.y));
                *(uint32_t*)(O + (size_t)(r0 + 8) * N + cn) =
                    pack_h2(__float2half_rn(acc[mi][ni][2] + bs.x),
                            __float2half_rn(acc[mi][ni][3] + bs.y));
            } else if (MODE == 1) {
                float2 ra = *(const float2*)(resid + (size_t)r0 * N + cn);
                float2 rb = *(const float2*)(resid + (size_t)(r0 + 8) * N + cn);
                *(float2*)(C + (size_t)r0 * N + cn) =
                    make_float2(acc[mi][ni][0] + bs.x + ra.x, acc[mi][ni][1] + bs.y + ra.y);
                *(float2*)(C + (size_t)(r0 + 8) * N + cn) =
                    make_float2(acc[mi][ni][2] + bs.x + rb.x, acc[mi][ni][3] + bs.y + rb.y);
            } else if (MODE == 2) {
                if (r0 < cnt) {
                    float v0 = fmaxf(acc[mi][ni][0] + bs.x, 0.f);
                    float v1 = fmaxf(acc[mi][ni][1] + bs.y, 0.f);
                    *(uint32_t*)(O + (size_t)(off + r0) * N + cn) =
                        pack_h2(__float2half_rn(v0), __float2half_rn(v1));
                }
                if (r0 + 8 < cnt) {
                    float v2 = fmaxf(acc[mi][ni][2] + bs.x, 0.f);
                    float v3 = fmaxf(acc[mi][ni][3] + bs.y, 0.f);
                    *(uint32_t*)(O + (size_t)(off + r0 + 8) * N + cn) =
                        pack_h2(__float2half_rn(v2), __float2half_rn(v3));
                }
            } else {
                if (r0 < cnt) {
                    int tok = g_perm[off + r0];
                    float2 xr = *(const float2*)(resid + (size_t)tok * N + cn);
                    *(float2*)(C + (size_t)tok * N + cn) =
                        make_float2(acc[mi][ni][0] + bs.x + xr.x, acc[mi][ni][1] + bs.y + xr.y);
                }
                if (r0 + 8 < cnt) {
                    int tok = g_perm[off + r0 + 8];
                    float2 xr = *(const float2*)(resid + (size_t)tok * N + cn);
                    *(float2*)(C + (size_t)tok * N + cn) =
                        make_float2(acc[mi][ni][2] + bs.x + xr.x, acc[mi][ni][3] + bs.y + xr.y);
                }
            }
        }
    }
}

// ---------------- layernorm with fp16 output ---------------------------------------
template <bool FP32OUT>
__global__ void ln_conv(const float* __restrict__ x, const float* __restrict__ g,
                        const float* __restrict__ bb, float* __restrict__ y,
                        __half* __restrict__ yh) {
    int t = blockIdx.x;
    const float* xr = x + (size_t)t * DMODEL;
    int d = threadIdx.x * 4;
    float4 v = *(const float4*)(xr + d);
    float s = v.x + v.y + v.z + v.w;
    float s2 = v.x * v.x + v.y * v.y + v.z * v.z + v.w * v.w;
#pragma unroll
    for (int o = 16; o; o >>= 1) {
        s += __shfl_xor_sync(0xffffffffu, s, o);
        s2 += __shfl_xor_sync(0xffffffffu, s2, o);
    }
    __shared__ float rs[8], rq[8];
    if ((threadIdx.x & 31) == 0) { rs[threadIdx.x >> 5] = s; rq[threadIdx.x >> 5] = s2; }
    __syncthreads();
    __shared__ float smean, srstd;
    if (threadIdx.x == 0) {
        float a = 0.f, b2 = 0.f;
#pragma unroll
        for (int i = 0; i < 8; i++) { a += rs[i]; b2 += rq[i]; }
        float mean = a * (1.f / DMODEL);
        float var = b2 * (1.f / DMODEL) - mean * mean;
        smean = mean; srstd = rsqrtf(var + 1e-5f);
    }
    __syncthreads();
    float mean = smean, rstd = srstd;
    float4 gv = *(const float4*)(g + d);
    float4 bv = *(const float4*)(bb + d);
    float4 o;
    o.x = (v.x - mean) * rstd * gv.x + bv.x;
    o.y = (v.y - mean) * rstd * gv.y + bv.y;
    o.z = (v.z - mean) * rstd * gv.z + bv.z;
    o.w = (v.w - mean) * rstd * gv.w + bv.w;
    if (FP32OUT) *(float4*)(y + (size_t)t * DMODEL + d) = o;
    conv4_h(o, yh + (size_t)t * DMODEL + d);
}

// ---------------- flash attention: fp16 in/out, single-pass QK and PV --------------
__global__ __launch_bounds__(128) void attn_mma(const __half* __restrict__ qkv,
                                                __half* __restrict__ oh) {
    __shared__ __half smem[64 * 72 * 5];
    __half* Qs = smem;
    __half* Kb[2] = {smem + 4608, smem + 9216};
    __half* Vb[2] = {smem + 13824, smem + 18432};

    const int qt = blockIdx.x, h = blockIdx.y, b = blockIdx.z;
    const int tid = threadIdx.x, lane = tid & 31, wid = tid >> 5;
    const int tok0 = b * SEQ + qt * 64;
    const int wq = wid * 16;
    const int lrow = tid >> 1, lcb = (tid & 1) * 32;

    {
        const __half* src = qkv + (size_t)(tok0 + lrow) * D3 + h * HDIM + lcb;
        uint32_t qd = sptr(Qs + lrow * 72 + lcb);
#pragma unroll
        for (int i = 0; i < 4; i++) cpa16(qd + i * 16, src + i * 8);
    }
    auto fill_kv = [&](int buf, int kt) {
        const __half* base = qkv + (size_t)(b * SEQ + kt * 64 + lrow) * D3 + h * HDIM + lcb;
        uint32_t kd = sptr(Kb[buf] + lrow * 72 + lcb);
        uint32_t vd = sptr(Vb[buf] + lrow * 72 + lcb);
#pragma unroll
        for (int i = 0; i < 4; i++) {
            cpa16(kd + i * 16, base + DMODEL + i * 8);
            cpa16(vd + i * 16, base + 2 * DMODEL + i * 8);
        }
        CP_COMMIT();
    };
    fill_kv(0, 0);

    float m_[2] = {-1e30f, -1e30f}, l_[2] = {0.f, 0.f};
    float O[8][4] = {};
    int buf = 0;

    for (int kt = 0; kt < 16; kt++) {
        CP_WAIT0();
        __syncthreads();
        if (kt + 1 < 16) fill_kv(buf ^ 1, kt + 1);
        const __half* Ks = Kb[buf];
        const __half* Vs = Vb[buf];

        float S[8][4] = {};
#pragma unroll
        for (int ks = 0; ks < 4; ks++) {
            uint32_t qf[4], kf[8][2];
            {
                int row = wq + (lane & 15);
                int col = ks * 16 + ((lane >> 4) & 1) * 8;
                ldsm4(qf, sptr(Qs + row * 72 + col));
            }
#pragma unroll
            for (int p = 0; p < 4; p++) {
                uint32_t r[4];
                int n = p * 16 + ((lane >> 4) & 1) * 8 + (lane & 7);
                int col = ks * 16 + ((lane >> 3) & 1) * 8;
                ldsm4(r, sptr(Ks + n * 72 + col));
                kf[2 * p][0] = r[0]; kf[2 * p][1] = r[1];
                kf[2 * p + 1][0] = r[2]; kf[2 * p + 1][1] = r[3];
            }
#pragma unroll
            for (int j = 0; j < 8; j++) mma16816(S[j], qf, kf[j]);
        }

        float fac[2];
#pragma unroll
        for (int h2 = 0; h2 < 2; h2++) {
            float rm = -1e30f;
#pragma unroll
            for (int j = 0; j < 8; j++) {
                S[j][2 * h2] *= 0.125f;
                S[j][2 * h2 + 1] *= 0.125f;
                rm = fmaxf(rm, fmaxf(S[j][2 * h2], S[j][2 * h2 + 1]));
            }
            rm = fmaxf(rm, __shfl_xor_sync(0xffffffffu, rm, 1));
            rm = fmaxf(rm, __shfl_xor_sync(0xffffffffu, rm, 2));
            float mn = fmaxf(m_[h2], rm);
            fac[h2] = __expf(m_[h2] - mn);
            float rsum = 0.f;
#pragma unroll
            for (int j = 0; j < 8; j++) {
                float p0 = __expf(S[j][2 * h2] - mn);
                float p1 = __expf(S[j][2 * h2 + 1] - mn);
                S[j][2 * h2] = p0; S[j][2 * h2 + 1] = p1;
                rsum += p0 + p1;
            }
            rsum += __shfl_xor_sync(0xffffffffu, rsum, 1);
            rsum += __shfl_xor_sync(0xffffffffu, rsum, 2);
            l_[h2] = l_[h2] * fac[h2] + rsum;
            m_[h2] = mn;
        }
#pragma unroll
        for (int j = 0; j < 8; j++) {
            O[j][0] *= fac[0]; O[j][1] *= fac[0];
            O[j][2] *= fac[1]; O[j][3] *= fac[1];
        }

#pragma unroll
        for (int ks = 0; ks < 4; ks++) {
            uint32_t pf[4];
            pf[0] = pack_h2(__float2half_rn(S[2 * ks][0]), __float2half_rn(S[2 * ks][1]));
            pf[1] = pack_h2(__float2half_rn(S[2 * ks][2]), __float2half_rn(S[2 * ks][3]));
            pf[2] = pack_h2(__float2half_rn(S[2 * ks + 1][0]), __float2half_rn(S[2 * ks + 1][1]));
            pf[3] = pack_h2(__float2half_rn(S[2 * ks + 1][2]), __float2half_rn(S[2 * ks + 1][3]));
            uint32_t vf[8][2];
#pragma unroll
            for (int p = 0; p < 4; p++) {
                uint32_t r[4];
                int k = ks * 16 + ((lane >> 3) & 1) * 8 + (lane & 7);
                int n = p * 16 + ((lane >> 4) & 1) * 8;
                ldsm4t(r, sptr(Vs + k * 72 + n));
                vf[2 * p][0] = r[0]; vf[2 * p][1] = r[1];
                vf[2 * p + 1][0] = r[2]; vf[2 * p + 1][1] = r[3];
            }
#pragma unroll
            for (int j = 0; j < 8; j++) mma16816(O[j], pf, vf[j]);
        }
        buf ^= 1;
    }

    float inv0 = 1.f / l_[0], inv1 = 1.f / l_[1];
    int r0 = tok0 + wq + (lane >> 2);
#pragma unroll
    for (int j = 0; j < 8; j++) {
        int col = h * HDIM + j * 8 + (lane & 3) * 2;
        *(uint32_t*)(oh + (size_t)r0 * DMODEL + col) =
            pack_h2(__float2half_rn(O[j][0] * inv0), __float2half_rn(O[j][1] * inv0));
        *(uint32_t*)(oh + (size_t)(r0 + 8) * DMODEL + col) =
            pack_h2(__float2half_rn(O[j][2] * inv1), __float2half_rn(O[j][3] * inv1));
    }
}

// ---------------- gate / bucketing -------------------------------------------------
__global__ void zero_kernel() {
    if (threadIdx.x < NTILES) { g_cnt[threadIdx.x] = 0; g_fill[threadIdx.x] = 0; }
}

__global__ void gate_kernel(const float* __restrict__ n2, const float* __restrict__ gw,
                            const float* __restrict__ gb, float* __restrict__ gate_out) {
    int t = blockIdx.x;
    const float* xr = n2 + (size_t)t * DMODEL;
    float lg[NTILES] = {};
    for (int d = threadIdx.x; d < DMODEL; d += 256) {
        float v = xr[d];
#pragma unroll
        for (int e = 0; e < NTILES; e++) lg[e] += v * gw[e * DMODEL + d];
    }
#pragma unroll
    for (int o = 16; o; o >>= 1)
#pragma unroll
        for (int e = 0; e < NTILES; e++) lg[e] += __shfl_xor_sync(0xffffffffu, lg[e], o);
    __shared__ float smv[8][NTILES];
    if ((threadIdx.x & 31) == 0)
#pragma unroll
        for (int e = 0; e < NTILES; e++) smv[threadIdx.x >> 5][e] = lg[e];
    __syncthreads();
    if (threadIdx.x == 0) {
        int best = 0; float bv = -1e30f;
#pragma unroll
        for (int e = 0; e < NTILES; e++) {
            float v = gb[e];
#pragma unroll
            for (int w = 0; w < 8; w++) v += smv[w][e];
            if (v > bv) { bv = v; best = e; }
        }
        g_tile_id[t] = best;
#pragma unroll
        for (int e = 0; e < NTILES; e++) gate_out[(size_t)t * NTILES + e] = (e == best) ? 1.f : 0.f;
        atomicAdd(&g_cnt[best], 1);
    }
}

__global__ void scan_kernel() {
    if (threadIdx.x == 0) {
        int a = 0;
        for (int e = 0; e < NTILES; e++) { g_off[e] = a; a += g_cnt[e]; }
    }
}

__global__ void scatter_kernel() {
    int t = blockIdx.x * 256 + threadIdx.x;
    int e = g_tile_id[t];
    int p = atomicAdd(&g_fill[e], 1);
    g_perm[g_off[e] + p] = t;
}

// ---------------- launch ------------------------------------------------------------
extern "C" void kernel_launch(void* const* d_in, const int* in_sizes, int n_in,
                              void* d_out, int out_size) {
    const float* x      = (const float*)d_in[0];
    const float* ln1_g  = (const float*)d_in[1];
    const float* ln1_b  = (const float*)d_in[2];
    const float* qkv_w  = (const float*)d_in[3];
    const float* qkv_b  = (const float*)d_in[4];
    const float* out_w  = (const float*)d_in[5];
    const float* out_b  = (const float*)d_in[6];
    const float* ln2_g  = (const float*)d_in[7];
    const float* ln2_b  = (const float*)d_in[8];
    const float* gate_w = (const float*)d_in[9];
    const float* gate_b = (const float*)d_in[10];
    const float* up_W   = (const float*)d_in[11];
    const float* up_b   = (const float*)d_in[12];
    const float* down_W = (const float*)d_in[13];
    const float* down_b = (const float*)d_in[14];

    float* outp = (float*)d_out;
    float* gate_out = outp + (size_t)NTOK * DMODEL;

    void* p;
    cudaGetSymbolAddress(&p, g_qkv);  __half* qkvh = (__half*)p;
    cudaGetSymbolAddress(&p, g_xres); float* xres = (float*)p;
    cudaGetSymbolAddress(&p, g_n2);   float* n2   = (float*)p;
    cudaGetSymbolAddress(&p, g_n1);   __half* n1h = (__half*)p;
    cudaGetSymbolAddress(&p, g_attn); __half* ath = (__half*)p;
    cudaGetSymbolAddress(&p, g_n2x);  __half* n2h = (__half*)p;
    cudaGetSymbolAddress(&p, g_h);    __half* hh = (__half*)p;
    cudaGetSymbolAddress(&p, g_qkvw); __half* qw = (__half*)p;
    cudaGetSymbolAddress(&p, g_outw); __half* ow = (__half*)p;
    cudaGetSymbolAddress(&p, g_upw);  __half* uw = (__half*)p;
    cudaGetSymbolAddress(&p, g_dnw);  __half* dw = (__half*)p;

    const int smem_nt = 4 * STG_NT_H * 2;  // 221184
    const int smem_t  = 4 * STG_T_H * 2;   // 217088
    cudaFuncSetAttribute(gemm_cp<0, false>, cudaFuncAttributeMaxDynamicSharedMemorySize, smem_nt);
    cudaFuncSetAttribute(gemm_cp<1, false>, cudaFuncAttributeMaxDynamicSharedMemorySize, smem_nt);
    cudaFuncSetAttribute(gemm_cp<2, true>, cudaFuncAttributeMaxDynamicSharedMemorySize, smem_t);
    cudaFuncSetAttribute(gemm_cp<3, true>, cudaFuncAttributeMaxDynamicSharedMemorySize, smem_t);

    // 0) weight convert
    wconv<<<D3 * DMODEL / 4096, 512>>>(qkv_w, qw);
    wconv<<<DMODEL * DMODEL / 4096, 512>>>(out_w, ow);
    wconv<<<NTILES * DMODEL * DFF / 4096, 512>>>(up_W, uw);
    wconv<<<NTILES * DFF * DMODEL / 4096, 512>>>(down_W, dw);

    // 1) LN1 (fp16 out)
    ln_conv<false><<<NTOK, 256>>>(x, ln1_g, ln1_b, nullptr, n1h);
    // 2) QKV projection -> fp16
    gemm_cp<0, false><<<dim3(D3 / 128, NTOK / 256), 512, smem_nt>>>(
        n1h, qw, qkv_b, nullptr, nullptr, qkvh, D3, DMODEL);
    // 3) attention
    attn_mma<<<dim3(SEQ / 64, NHEAD, NB), 128>>>(qkvh, ath);
    // 4) out projection + residual -> fp32
    gemm_cp<1, false><<<dim3(DMODEL / 128, NTOK / 256), 512, smem_nt>>>(
        ath, ow, out_b, x, xres, nullptr, DMODEL, DMODEL);
    // 5) LN2 (fp32 + fp16)
    ln_conv<true><<<NTOK, 256>>>(xres, ln2_g, ln2_b, n2, n2h);
    // 6) gate + bucketing
    zero_kernel<<<1, 32>>>();
    gate_kernel<<<NTOK, 256>>>(n2, gate_w, gate_b, gate_out);
    scan_kernel<<<1, 32>>>();
    scatter_kernel<<<NTOK / 256, 256>>>();
    // 7) FFN
    gemm_cp<2, true><<<dim3(DFF / 128, NTOK / 256, NTILES), 512, smem_t>>>(
        n2h, uw, up_b, nullptr, nullptr, hh, DFF, DMODEL);
    gemm_cp<3, true><<<dim3(DMODEL / 128, NTOK / 256, NTILES), 512, smem_t>>>(
        hh, dw, down_b, xres, outp, nullptr, DMODEL, DFF);
}

// round 17
// speedup vs baseline: 1.6581x; 1.6581x over previous
#include <cuda_runtime.h>
#include <cuda_fp16.h>
#include <math.h>
#include <stdint.h>

#define NTOK 4096
#define DMODEL 1024
#define D3 3072
#define NHEAD 16
#define HDIM 64
#define SEQ 1024
#define NB 4
#define NTILES 8
#define DFF 4096

// ---------------- scratch (device globals) -------------------------------------
__device__ __half g_qkv[NTOK * D3];
__device__ float g_xres[NTOK * DMODEL];
__device__ float g_n2[NTOK * DMODEL];
__device__ __half g_n1[NTOK * DMODEL];
__device__ __half g_attn[NTOK * DMODEL];
__device__ __half g_n2x[NTOK * DMODEL];
__device__ __half g_h[(size_t)NTOK * DFF];
__device__ __half g_qkvw[D3 * DMODEL];
__device__ __half g_outw[DMODEL * DMODEL];
__device__ __half g_upw[(size_t)NTILES * DMODEL * DFF];
__device__ __half g_dnw[(size_t)NTILES * DFF * DMODEL];
__device__ int g_tile_id[NTOK];
__device__ int g_perm[NTOK];
__device__ int g_cnt[NTILES];
__device__ int g_off[NTILES];
__device__ int g_fill[NTILES];

// ---------------- helpers -------------------------------------------------------
__device__ __forceinline__ uint32_t sptr(const void* p) {
    return (uint32_t)__cvta_generic_to_shared(p);
}
__device__ __forceinline__ uint32_t pack_h2(__half a, __half b) {
    return (uint32_t)__half_as_ushort(a) | ((uint32_t)__half_as_ushort(b) << 16);
}
__device__ __forceinline__ void conv4_h(float4 v, __half* d) {
    *(uint32_t*)(d)     = pack_h2(__float2half_rn(v.x), __float2half_rn(v.y));
    *(uint32_t*)(d + 2) = pack_h2(__float2half_rn(v.z), __float2half_rn(v.w));
}
__device__ __forceinline__ void ldsm4(uint32_t* r, uint32_t a) {
    asm volatile("ldmatrix.sync.aligned.m8n8.x4.shared.b16 {%0,%1,%2,%3}, [%4];"
                 : "=r"(r[0]), "=r"(r[1]), "=r"(r[2]), "=r"(r[3]) : "r"(a));
}
__device__ __forceinline__ void ldsm4t(uint32_t* r, uint32_t a) {
    asm volatile("ldmatrix.sync.aligned.m8n8.x4.trans.shared.b16 {%0,%1,%2,%3}, [%4];"
                 : "=r"(r[0]), "=r"(r[1]), "=r"(r[2]), "=r"(r[3]) : "r"(a));
}
__device__ __forceinline__ void mma16816(float* c, const uint32_t* a, const uint32_t* b) {
    asm volatile(
        "mma.sync.aligned.m16n8k16.row.col.f32.f16.f16.f32 "
        "{%0,%1,%2,%3}, {%4,%5,%6,%7}, {%8,%9}, {%0,%1,%2,%3};"
        : "+f"(c[0]), "+f"(c[1]), "+f"(c[2]), "+f"(c[3])
        : "r"(a[0]), "r"(a[1]), "r"(a[2]), "r"(a[3]), "r"(b[0]), "r"(b[1]));
}
__device__ __forceinline__ void cpa16(uint32_t s, const void* g) {
    asm volatile("cp.async.cg.shared.global [%0], [%1], 16;" :: "r"(s), "l"(g));
}
#define CP_COMMIT() asm volatile("cp.async.commit_group;" ::: "memory")
#define CP_WAIT2() asm volatile("cp.async.wait_group 2;" ::: "memory")
#define CP_WAIT0() asm volatile("cp.async.wait_group 0;" ::: "memory")

// ---------------- weight convert (8 floats / thread, 512-thr blocks) ---------------
__global__ void wconv(const float* __restrict__ src, __half* __restrict__ d) {
    size_t i = (size_t)blockIdx.x * 512 + threadIdx.x;
    float4 v0 = *(const float4*)(src + i * 8);
    float4 v1 = *(const float4*)(src + i * 8 + 4);
    conv4_h(v0, d + i * 8);
    conv4_h(v1, d + i * 8 + 4);
}

// ---------------- GEMM core: one 64-K chunk, single-pass fp16, warp tile 32x32 ----
template <bool BT>
__device__ __forceinline__ void mma_compute(const __half* As, const __half* Bs,
                                            float (*acc)[4][4], int lane, int wm, int wn) {
#pragma unroll
    for (int s = 0; s < 4; s++) {
        const int ks = s * 16;
        uint32_t af[2][4], bf[4][2];
#pragma unroll
        for (int mi = 0; mi < 2; mi++) {
            int row = wm * 32 + mi * 16 + (lane & 15);
            int col = ks + ((lane >> 4) & 1) * 8;
            ldsm4(af[mi], sptr(As + row * 72 + col));
        }
#pragma unroll
        for (int p = 0; p < 2; p++) {
            uint32_t r[4];
            if (!BT) {
                int n = wn * 32 + p * 16 + ((lane >> 4) & 1) * 8 + (lane & 7);
                int col = ks + ((lane >> 3) & 1) * 8;
                ldsm4(r, sptr(Bs + n * 72 + col));
            } else {
                int k = ks + ((lane >> 3) & 1) * 8 + (lane & 7);
                int n = wn * 32 + p * 16 + ((lane >> 4) & 1) * 8;
                ldsm4t(r, sptr(Bs + k * 136 + n));
            }
            bf[2 * p][0] = r[0]; bf[2 * p][1] = r[1];
            bf[2 * p + 1][0] = r[2]; bf[2 * p + 1][1] = r[3];
        }
#pragma unroll
        for (int mi = 0; mi < 2; mi++)
#pragma unroll
            for (int ni = 0; ni < 4; ni++)
                mma16816(acc[mi][ni], af[mi], bf[ni]);
    }
}

// ---------------- GEMM: 512 thr, 64-K chunks, 4-stage, 1 barrier/chunk -------------
// MODE 0: +bias -> fp16 O          MODE 1: +bias +resid -> fp32 C
// MODE 2: gather A via perm, +bias, relu -> fp16 O (compact), BT
// MODE 3: A compact, +bias +resid, scatter -> fp32 C, BT
#define BOFF 18432
#define STG_NT 36864
#define STG_T 35840

template <int MODE, bool BT>
__global__ __launch_bounds__(512, 1) void gemm_cp(
    const __half* __restrict__ Ah, const __half* __restrict__ W,
    const float* __restrict__ bias, const float* __restrict__ resid,
    float* __restrict__ C, __half* __restrict__ O, int N, int K) {
    constexpr int STG = BT ? STG_T : STG_NT;
    extern __shared__ __half dsm[];
    const int tid = threadIdx.x, lane = tid & 31, w = tid >> 5;
    const int wm = w & 3, wn = w >> 2;
    const int bn = blockIdx.x * 128, bm = blockIdx.y * 128;
    int cnt = 0, off = 0;
    if (MODE >= 2) {
        const int t = blockIdx.z;
        cnt = g_cnt[t];
        if (bm >= cnt) return;
        off = g_off[t];
        W += (size_t)t * N * K;
        bias += (size_t)t * N;
    }
    const uint32_t sb = sptr(dsm);
    const int ar0 = tid >> 3, kc = tid & 7;
    const uint32_t adst0 = (uint32_t)(ar0 * 144 + kc * 16);
    const uint32_t adst1 = (uint32_t)((ar0 + 64) * 144 + kc * 16);
    size_t abase0, abase1;
    if (MODE <= 1) {
        abase0 = (size_t)(bm + ar0) * K;
        abase1 = (size_t)(bm + ar0 + 64) * K;
    } else if (MODE == 2) {
        int t0 = (bm + ar0 < cnt) ? g_perm[off + bm + ar0] : 0;
        int t1 = (bm + ar0 + 64 < cnt) ? g_perm[off + bm + ar0 + 64] : 0;
        abase0 = (size_t)t0 * K;
        abase1 = (size_t)t1 * K;
    } else {
        int r0c = (bm + ar0 < cnt) ? bm + ar0 : 0;
        int r1c = (bm + ar0 + 64 < cnt) ? bm + ar0 + 64 : 0;
        abase0 = (size_t)(off + r0c) * K;
        abase1 = (size_t)(off + r1c) * K;
    }
    size_t bb0 = 0, bb1 = 0;
    uint32_t bd0 = 0, bd1 = 0;
    int bkc = 0, btr = 0, btc = 0;
    if (!BT) {
        bb0 = (size_t)(bn + ar0) * K;
        bb1 = (size_t)(bn + ar0 + 64) * K;
        bd0 = BOFF + adst0;
        bd1 = BOFF + adst1;
        bkc = kc;
    } else {
        btr = tid >> 4;
        btc = tid & 15;
        bd0 = (uint32_t)(BOFF + btr * 272 + btc * 16);
        bd1 = (uint32_t)(BOFF + (btr + 32) * 272 + btc * 16);
    }
    const int NC = K >> 6;
    auto fill = [&](int s, int c) {
        const int k0 = c * 64;
        const uint32_t st = sb + s * STG;
        cpa16(st + adst0, Ah + abase0 + k0 + kc * 8);
        cpa16(st + adst1, Ah + abase1 + k0 + kc * 8);
        if (!BT) {
            cpa16(st + bd0, W + bb0 + k0 + bkc * 8);
            cpa16(st + bd1, W + bb1 + k0 + bkc * 8);
        } else {
            cpa16(st + bd0, W + (size_t)(k0 + btr) * N + bn + btc * 8);
            cpa16(st + bd1, W + (size_t)(k0 + btr + 32) * N + bn + btc * 8);
        }
        CP_COMMIT();
    };
    fill(0, 0);
    if (NC > 1) fill(1, 1);
    if (NC > 2) fill(2, 2);
    float acc[2][4][4] = {};
    for (int c = 0; c < NC; c++) {
        if (c + 3 < NC) CP_WAIT2(); else CP_WAIT0();
        __syncthreads();  // data visible; all warps past chunk c-1's reads
        if (c + 3 < NC) fill((c + 3) & 3, c + 3);  // targets stage (c-1)&3: safe
        const __half* b0 = dsm + (c & 3) * (STG / 2);
        mma_compute<BT>(b0, b0 + BOFF / 2, acc, lane, wm, wn);
    }
    // ---- epilogue
#pragma unroll
    for (int mi = 0; mi < 2; mi++) {
        int r0 = bm + wm * 32 + mi * 16 + (lane >> 2);
#pragma unroll
        for (int ni = 0; ni < 4; ni++) {
            int cn = bn + wn * 32 + ni * 8 + (lane & 3) * 2;
            float2 bs = *(const float2*)(bias + cn);
            if (MODE == 0) {
                *(uint32_t*)(O + (size_t)r0 * N + cn) =
                    pack_h2(__float2half_rn(acc[mi][ni][0] + bs.x),
                            __float2half_rn(acc[mi][ni][1] + bs.y));
                *(uint32_t*)(O + (size_t)(r0 + 8) * N + cn) =
                    pack_h2(__float2half_rn(acc[mi][ni][2] + bs.x),
                            __float2half_rn(acc[mi][ni][3] + bs.y));
            } else if (MODE == 1) {
                float2 ra = *(const float2*)(resid + (size_t)r0 * N + cn);
                float2 rb = *(const float2*)(resid + (size_t)(r0 + 8) * N + cn);
                *(float2*)(C + (size_t)r0 * N + cn) =
                    make_float2(acc[mi][ni][0] + bs.x + ra.x, acc[mi][ni][1] + bs.y + ra.y);
                *(float2*)(C + (size_t)(r0 + 8) * N + cn) =
                    make_float2(acc[mi][ni][2] + bs.x + rb.x, acc[mi][ni][3] + bs.y + rb.y);
            } else if (MODE == 2) {
                if (r0 < cnt) {
                    float v0 = fmaxf(acc[mi][ni][0] + bs.x, 0.f);
                    float v1 = fmaxf(acc[mi][ni][1] + bs.y, 0.f);
                    *(uint32_t*)(O + (size_t)(off + r0) * N + cn) =
                        pack_h2(__float2half_rn(v0), __float2half_rn(v1));
                }
                if (r0 + 8 < cnt) {
                    float v2 = fmaxf(acc[mi][ni][2] + bs.x, 0.f);
                    float v3 = fmaxf(acc[mi][ni][3] + bs.y, 0.f);
                    *(uint32_t*)(O + (size_t)(off + r0 + 8) * N + cn) =
                        pack_h2(__float2half_rn(v2), __float2half_rn(v3));
                }
            } else {
                if (r0 < cnt) {
                    int tok = g_perm[off + r0];
                    float2 xr = *(const float2*)(resid + (size_t)tok * N + cn);
                    *(float2*)(C + (size_t)tok * N + cn) =
                        make_float2(acc[mi][ni][0] + bs.x + xr.x, acc[mi][ni][1] + bs.y + xr.y);
                }
                if (r0 + 8 < cnt) {
                    int tok = g_perm[off + r0 + 8];
                    float2 xr = *(const float2*)(resid + (size_t)tok * N + cn);
                    *(float2*)(C + (size_t)tok * N + cn) =
                        make_float2(acc[mi][ni][2] + bs.x + xr.x, acc[mi][ni][3] + bs.y + xr.y);
                }
            }
        }
    }
}

// ---------------- layernorm with fp16 output ---------------------------------------
template <bool FP32OUT>
__global__ void ln_conv(const float* __restrict__ x, const float* __restrict__ g,
                        const float* __restrict__ bb, float* __restrict__ y,
                        __half* __restrict__ yh) {
    int t = blockIdx.x;
    const float* xr = x + (size_t)t * DMODEL;
    int d = threadIdx.x * 4;
    float4 v = *(const float4*)(xr + d);
    float s = v.x + v.y + v.z + v.w;
    float s2 = v.x * v.x + v.y * v.y + v.z * v.z + v.w * v.w;
#pragma unroll
    for (int o = 16; o; o >>= 1) {
        s += __shfl_xor_sync(0xffffffffu, s, o);
        s2 += __shfl_xor_sync(0xffffffffu, s2, o);
    }
    __shared__ float rs[8], rq[8];
    if ((threadIdx.x & 31) == 0) { rs[threadIdx.x >> 5] = s; rq[threadIdx.x >> 5] = s2; }
    __syncthreads();
    __shared__ float smean, srstd;
    if (threadIdx.x == 0) {
        float a = 0.f, b2 = 0.f;
#pragma unroll
        for (int i = 0; i < 8; i++) { a += rs[i]; b2 += rq[i]; }
        float mean = a * (1.f / DMODEL);
        float var = b2 * (1.f / DMODEL) - mean * mean;
        smean = mean; srstd = rsqrtf(var + 1e-5f);
    }
    __syncthreads();
    float mean = smean, rstd = srstd;
    float4 gv = *(const float4*)(g + d);
    float4 bv = *(const float4*)(bb + d);
    float4 o;
    o.x = (v.x - mean) * rstd * gv.x + bv.x;
    o.y = (v.y - mean) * rstd * gv.y + bv.y;
    o.z = (v.z - mean) * rstd * gv.z + bv.z;
    o.w = (v.w - mean) * rstd * gv.w + bv.w;
    if (FP32OUT) *(float4*)(y + (size_t)t * DMODEL + d) = o;
    conv4_h(o, yh + (size_t)t * DMODEL + d);
}

// ---------------- flash attention: fp16 in/out, single-pass QK and PV --------------
__global__ __launch_bounds__(128) void attn_mma(const __half* __restrict__ qkv,
                                                __half* __restrict__ oh) {
    __shared__ __half smem[64 * 72 * 5];
    __half* Qs = smem;
    __half* Kb[2] = {smem + 4608, smem + 9216};
    __half* Vb[2] = {smem + 13824, smem + 18432};

    const int qt = blockIdx.x, h = blockIdx.y, b = blockIdx.z;
    const int tid = threadIdx.x, lane = tid & 31, wid = tid >> 5;
    const int tok0 = b * SEQ + qt * 64;
    const int wq = wid * 16;
    const int lrow = tid >> 1, lcb = (tid & 1) * 32;

    {
        const __half* src = qkv + (size_t)(tok0 + lrow) * D3 + h * HDIM + lcb;
        uint32_t qd = sptr(Qs + lrow * 72 + lcb);
#pragma unroll
        for (int i = 0; i < 4; i++) cpa16(qd + i * 16, src + i * 8);
    }
    auto fill_kv = [&](int buf, int kt) {
        const __half* base = qkv + (size_t)(b * SEQ + kt * 64 + lrow) * D3 + h * HDIM + lcb;
        uint32_t kd = sptr(Kb[buf] + lrow * 72 + lcb);
        uint32_t vd = sptr(Vb[buf] + lrow * 72 + lcb);
#pragma unroll
        for (int i = 0; i < 4; i++) {
            cpa16(kd + i * 16, base + DMODEL + i * 8);
            cpa16(vd + i * 16, base + 2 * DMODEL + i * 8);
        }
        CP_COMMIT();
    };
    fill_kv(0, 0);

    float m_[2] = {-1e30f, -1e30f}, l_[2] = {0.f, 0.f};
    float O[8][4] = {};
    int buf = 0;

    for (int kt = 0; kt < 16; kt++) {
        CP_WAIT0();
        __syncthreads();
        if (kt + 1 < 16) fill_kv(buf ^ 1, kt + 1);
        const __half* Ks = Kb[buf];
        const __half* Vs = Vb[buf];

        float S[8][4] = {};
#pragma unroll
        for (int ks = 0; ks < 4; ks++) {
            uint32_t qf[4], kf[8][2];
            {
                int row = wq + (lane & 15);
                int col = ks * 16 + ((lane >> 4) & 1) * 8;
                ldsm4(qf, sptr(Qs + row * 72 + col));
            }
#pragma unroll
            for (int p = 0; p < 4; p++) {
                uint32_t r[4];
                int n = p * 16 + ((lane >> 4) & 1) * 8 + (lane & 7);
                int col = ks * 16 + ((lane >> 3) & 1) * 8;
                ldsm4(r, sptr(Ks + n * 72 + col));
                kf[2 * p][0] = r[0]; kf[2 * p][1] = r[1];
                kf[2 * p + 1][0] = r[2]; kf[2 * p + 1][1] = r[3];
            }
#pragma unroll
            for (int j = 0; j < 8; j++) mma16816(S[j], qf, kf[j]);
        }

        float fac[2];
#pragma unroll
        for (int h2 = 0; h2 < 2; h2++) {
            float rm = -1e30f;
#pragma unroll
            for (int j = 0; j < 8; j++) {
                S[j][2 * h2] *= 0.125f;
                S[j][2 * h2 + 1] *= 0.125f;
                rm = fmaxf(rm, fmaxf(S[j][2 * h2], S[j][2 * h2 + 1]));
            }
            rm = fmaxf(rm, __shfl_xor_sync(0xffffffffu, rm, 1));
            rm = fmaxf(rm, __shfl_xor_sync(0xffffffffu, rm, 2));
            float mn = fmaxf(m_[h2], rm);
            fac[h2] = __expf(m_[h2] - mn);
            float rsum = 0.f;
#pragma unroll
            for (int j = 0; j < 8; j++) {
                float p0 = __expf(S[j][2 * h2] - mn);
                float p1 = __expf(S[j][2 * h2 + 1] - mn);
                S[j][2 * h2] = p0; S[j][2 * h2 + 1] = p1;
                rsum += p0 + p1;
            }
            rsum += __shfl_xor_sync(0xffffffffu, rsum, 1);
            rsum += __shfl_xor_sync(0xffffffffu, rsum, 2);
            l_[h2] = l_[h2] * fac[h2] + rsum;
            m_[h2] = mn;
        }
#pragma unroll
        for (int j = 0; j < 8; j++) {
            O[j][0] *= fac[0]; O[j][1] *= fac[0];
            O[j][2] *= fac[1]; O[j][3] *= fac[1];
        }

#pragma unroll
        for (int ks = 0; ks < 4; ks++) {
            uint32_t pf[4];
            pf[0] = pack_h2(__float2half_rn(S[2 * ks][0]), __float2half_rn(S[2 * ks][1]));
            pf[1] = pack_h2(__float2half_rn(S[2 * ks][2]), __float2half_rn(S[2 * ks][3]));
            pf[2] = pack_h2(__float2half_rn(S[2 * ks + 1][0]), __float2half_rn(S[2 * ks + 1][1]));
            pf[3] = pack_h2(__float2half_rn(S[2 * ks + 1][2]), __float2half_rn(S[2 * ks + 1][3]));
            uint32_t vf[8][2];
#pragma unroll
            for (int p = 0; p < 4; p++) {
                uint32_t r[4];
                int k = ks * 16 + ((lane >> 3) & 1) * 8 + (lane & 7);
                int n = p * 16 + ((lane >> 4) & 1) * 8;
                ldsm4t(r, sptr(Vs + k * 72 + n));
                vf[2 * p][0] = r[0]; vf[2 * p][1] = r[1];
                vf[2 * p + 1][0] = r[2]; vf[2 * p + 1][1] = r[3];
            }
#pragma unroll
            for (int j = 0; j < 8; j++) mma16816(O[j], pf, vf[j]);
        }
        buf ^= 1;
    }

    float inv0 = 1.f / l_[0], inv1 = 1.f / l_[1];
    int r0 = tok0 + wq + (lane >> 2);
#pragma unroll
    for (int j = 0; j < 8; j++) {
        int col = h * HDIM + j * 8 + (lane & 3) * 2;
        *(uint32_t*)(oh + (size_t)r0 * DMODEL + col) =
            pack_h2(__float2half_rn(O[j][0] * inv0), __float2half_rn(O[j][1] * inv0));
        *(uint32_t*)(oh + (size_t)(r0 + 8) * DMODEL + col) =
            pack_h2(__float2half_rn(O[j][2] * inv1), __float2half_rn(O[j][3] * inv1));
    }
}

// ---------------- gate / bucketing -------------------------------------------------
__global__ void zero_kernel() {
    if (threadIdx.x < NTILES) { g_cnt[threadIdx.x] = 0; g_fill[threadIdx.x] = 0; }
}

__global__ void gate_kernel(const float* __restrict__ n2, const float* __restrict__ gw,
                            const float* __restrict__ gb, float* __restrict__ gate_out) {
    int t = blockIdx.x;
    const float* xr = n2 + (size_t)t * DMODEL;
    float lg[NTILES] = {};
    for (int d = threadIdx.x; d < DMODEL; d += 256) {
        float v = xr[d];
#pragma unroll
        for (int e = 0; e < NTILES; e++) lg[e] += v * gw[e * DMODEL + d];
    }
#pragma unroll
    for (int o = 16; o; o >>= 1)
#pragma unroll
        for (int e = 0; e < NTILES; e++) lg[e] += __shfl_xor_sync(0xffffffffu, lg[e], o);
    __shared__ float smv[8][NTILES];
    if ((threadIdx.x & 31) == 0)
#pragma unroll
        for (int e = 0; e < NTILES; e++) smv[threadIdx.x >> 5][e] = lg[e];
    __syncthreads();
    if (threadIdx.x == 0) {
        int best = 0; float bv = -1e30f;
#pragma unroll
        for (int e = 0; e < NTILES; e++) {
            float v = gb[e];
#pragma unroll
            for (int w = 0; w < 8; w++) v += smv[w][e];
            if (v > bv) { bv = v; best = e; }
        }
        g_tile_id[t] = best;
#pragma unroll
        for (int e = 0; e < NTILES; e++) gate_out[(size_t)t * NTILES + e] = (e == best) ? 1.f : 0.f;
        atomicAdd(&g_cnt[best], 1);
    }
}

__global__ void scan_kernel() {
    if (threadIdx.x == 0) {
        int a = 0;
        for (int e = 0; e < NTILES; e++) { g_off[e] = a; a += g_cnt[e]; }
    }
}

__global__ void scatter_kernel() {
    int t = blockIdx.x * 256 + threadIdx.x;
    int e = g_tile_id[t];
    int p = atomicAdd(&g_fill[e], 1);
    g_perm[g_off[e] + p] = t;
}

// ---------------- launch ------------------------------------------------------------
extern "C" void kernel_launch(void* const* d_in, const int* in_sizes, int n_in,
                              void* d_out, int out_size) {
    const float* x      = (const float*)d_in[0];
    const float* ln1_g  = (const float*)d_in[1];
    const float* ln1_b  = (const float*)d_in[2];
    const float* qkv_w  = (const float*)d_in[3];
    const float* qkv_b  = (const float*)d_in[4];
    const float* out_w  = (const float*)d_in[5];
    const float* out_b  = (const float*)d_in[6];
    const float* ln2_g  = (const float*)d_in[7];
    const float* ln2_b  = (const float*)d_in[8];
    const float* gate_w = (const float*)d_in[9];
    const float* gate_b = (const float*)d_in[10];
    const float* up_W   = (const float*)d_in[11];
    const float* up_b   = (const float*)d_in[12];
    const float* down_W = (const float*)d_in[13];
    const float* down_b = (const float*)d_in[14];

    float* outp = (float*)d_out;
    float* gate_out = outp + (size_t)NTOK * DMODEL;

    void* p;
    cudaGetSymbolAddress(&p, g_qkv);  __half* qkvh = (__half*)p;
    cudaGetSymbolAddress(&p, g_xres); float* xres = (float*)p;
    cudaGetSymbolAddress(&p, g_n2);   float* n2   = (float*)p;
    cudaGetSymbolAddress(&p, g_n1);   __half* n1h = (__half*)p;
    cudaGetSymbolAddress(&p, g_attn); __half* ath = (__half*)p;
    cudaGetSymbolAddress(&p, g_n2x);  __half* n2h = (__half*)p;
    cudaGetSymbolAddress(&p, g_h);    __half* hh = (__half*)p;
    cudaGetSymbolAddress(&p, g_qkvw); __half* qw = (__half*)p;
    cudaGetSymbolAddress(&p, g_outw); __half* ow = (__half*)p;
    cudaGetSymbolAddress(&p, g_upw);  __half* uw = (__half*)p;
    cudaGetSymbolAddress(&p, g_dnw);  __half* dw = (__half*)p;

    const int smem_nt = 4 * STG_NT;
    const int smem_t  = 4 * STG_T;
    cudaFuncSetAttribute(gemm_cp<0, false>, cudaFuncAttributeMaxDynamicSharedMemorySize, smem_nt);
    cudaFuncSetAttribute(gemm_cp<1, false>, cudaFuncAttributeMaxDynamicSharedMemorySize, smem_nt);
    cudaFuncSetAttribute(gemm_cp<2, true>, cudaFuncAttributeMaxDynamicSharedMemorySize, smem_t);
    cudaFuncSetAttribute(gemm_cp<3, true>, cudaFuncAttributeMaxDynamicSharedMemorySize, smem_t);

    // 0) weight convert (8 floats/thread)
    wconv<<<D3 * DMODEL / 4096, 512>>>(qkv_w, qw);
    wconv<<<DMODEL * DMODEL / 4096, 512>>>(out_w, ow);
    wconv<<<NTILES * DMODEL * DFF / 4096, 512>>>(up_W, uw);
    wconv<<<NTILES * DFF * DMODEL / 4096, 512>>>(down_W, dw);

    // 1) LN1 (fp16 out)
    ln_conv<false><<<NTOK, 256>>>(x, ln1_g, ln1_b, nullptr, n1h);
    // 2) QKV projection -> fp16
    gemm_cp<0, false><<<dim3(D3 / 128, NTOK / 128), 512, smem_nt>>>(
        n1h, qw, qkv_b, nullptr, nullptr, qkvh, D3, DMODEL);
    // 3) attention
    attn_mma<<<dim3(SEQ / 64, NHEAD, NB), 128>>>(qkvh, ath);
    // 4) out projection + residual -> fp32
    gemm_cp<1, false><<<dim3(DMODEL / 128, NTOK / 128), 512, smem_nt>>>(
        ath, ow, out_b, x, xres, nullptr, DMODEL, DMODEL);
    // 5) LN2 (fp32 + fp16)
    ln_conv<true><<<NTOK, 256>>>(xres, ln2_g, ln2_b, n2, n2h);
    // 6) gate + bucketing
    zero_kernel<<<1, 32>>>();
    gate_kernel<<<NTOK, 256>>>(n2, gate_w, gate_b, gate_out);
    scan_kernel<<<1, 32>>>();
    scatter_kernel<<<NTOK / 256, 256>>>();
    // 7) FFN
    gemm_cp<2, true><<<dim3(DFF / 128, NTOK / 128, NTILES), 512, smem_t>>>(
        n2h, uw, up_b, nullptr, nullptr, hh, DFF, DMODEL);
    gemm_cp<3, true><<<dim3(DMODEL / 128, NTOK / 128, NTILES), 512, smem_t>>>(
        hh, dw, down_b, xres, outp, nullptr, DMODEL, DFF);
}